// round 10
// baseline (speedup 1.0000x reference)
#include <cuda_runtime.h>
#include <cstdint>

#define B_ 2
#define T_ 2048
#define C_ 1024
#define H_ 16
#define D_ 64

// ---- scratch (no cudaMalloc allowed) ----
__device__ float g_q[(size_t)B_ * H_ * T_ * D_];          // [b][h][t][d]
__device__ float g_k[(size_t)B_ * H_ * T_ * D_];          // [b][h][t][d]
__device__ float g_v[(size_t)B_ * H_ * D_ * T_];          // [b][h][d][t]  (TRANSPOSED)
__device__ float g_s[(size_t)B_ * H_ * T_ * T_];          // [b][h][q][k]
__device__ float g_o[(size_t)B_ * T_ * C_];               // [b][t][h*64+d]

__device__ __forceinline__ float tf32_rna(float x) {
    float y;
    asm("cvt.rna.tf32.f32 %0, %1;" : "=f"(y) : "f"(x));
    return y;
}

// m16n8k8 tf32 mma (baseline PTX, maps to HMMA on sm_103)
#define MMA_TF32(c, a, b)                                                        \
    asm volatile("mma.sync.aligned.m16n8k8.row.col.f32.tf32.tf32.f32 "           \
                 "{%0,%1,%2,%3}, {%4,%5,%6,%7}, {%8,%9}, {%0,%1,%2,%3};"         \
                 : "+f"((c)[0]), "+f"((c)[1]), "+f"((c)[2]), "+f"((c)[3])        \
                 : "r"((a)[0]), "r"((a)[1]), "r"((a)[2]), "r"((a)[3]),           \
                   "r"((b)[0]), "r"((b)[1]))

// ============================================================================
// Tensor-core GEMM:  C[m,n] = sum_k A[m,k] * B[n,k]   (NT; B row n, col k)
// CTA: 128 x BN x 32, 256 thr (8 warps).
//   BN=128: warps 2m x 4n (warp tile 64x32);  BN=64: warps 4m x 2n (32x32).
// SPLIT: 2-term tf32 split (hi*hi + hi*lo + lo*hi) -> fp32-class accuracy.
// DB: smem buffers (2 = double-buffered, one barrier per chunk).
// MODE 0: QK proj -> out[((b*H+h)*T+t)*64+d]
// MODE 4: V proj  -> out[((b*H+h)*64+d)*T+t]   (transposed)
// MODE 1: S       -> out[z*T*T + m*T + n] * 8   (streaming stores)
// MODE 2: PV      -> out[(b*T+m)*C + h*64 + n]  (streaming P loads)
// MODE 3: O proj  -> out[m*C+n] + bias[n]
// ============================================================================
template <int MODE, bool SPLIT, int BN, int DB>
__global__ __launch_bounds__(256, 2) void mma_gemm(
    const float* __restrict__ A, const float* __restrict__ Bm,
    float* __restrict__ Cout, const float* __restrict__ bias,
    int K, int lda, int ldb, long long sA, long long sB)
{
    constexpr int BM = 128, BKP = 36;
    constexpr int GM = (BN == 128) ? 2 : 4;       // warp grid (m)
    constexpr int WM = (BN == 128) ? 4 : 2;       // m16 tiles per warp
    constexpr int WN = 4;                         // n8 tiles per warp
    constexpr int NA4 = 4;                        // A float4s per thread per chunk
    constexpr int NB4 = BN / 32;                  // B float4s per thread per chunk
    constexpr int ASZ = BM * BKP;
    constexpr int BSZ = BN * BKP;
    constexpr int NPART = SPLIT ? 2 : 1;
    constexpr int BUFF = NPART * (ASZ + BSZ);     // floats per buffer

    extern __shared__ float sm[];

    const int tid = threadIdx.x;
    const int w   = tid >> 5;
    const int lane = tid & 31;
    const int gid = lane >> 2;     // 0..7
    const int tig = lane & 3;      // 0..3
    const int wm = w % GM;
    const int wn = w / GM;
    const int warp_m0 = wm * WM * 16;
    const int warp_n0 = wn * WN * 8;

    const int z = blockIdx.z;
    const float* Ab = A + (long long)z * sA;
    const float* Bb = Bm + (long long)z * sB;
    const int m0 = blockIdx.y * BM;
    const int n0 = blockIdx.x * BN;

    const int ar = tid >> 3;            // 0..31
    const int ac = (tid & 7) * 4;       // 0,4,...,28

    float acc[WM][WN][4];
#pragma unroll
    for (int i = 0; i < WM; i++)
#pragma unroll
        for (int j = 0; j < WN; j++)
#pragma unroll
            for (int t = 0; t < 4; t++) acc[i][j][t] = 0.0f;

    float4 pa[NA4], pb[NB4];
    auto loadA = [&](int k0) {
#pragma unroll
        for (int i = 0; i < NA4; i++) {
            const float4* p = (const float4*)(Ab + (long long)(m0 + ar + i * 32) * lda + k0 + ac);
            pa[i] = (MODE == 2) ? __ldcs(p) : *p;   // P is streamed once
        }
    };
    auto loadB = [&](int k0) {
#pragma unroll
        for (int i = 0; i < NB4; i++)
            pb[i] = *(const float4*)(Bb + (long long)(n0 + ar + i * 32) * ldb + k0 + ac);
    };
    auto stage = [&](int buf) {
        float* Ah = sm + buf * BUFF;
        float* Al = Ah + (SPLIT ? ASZ : 0);
        float* Bh = Ah + NPART * ASZ;
        float* Bl = Bh + (SPLIT ? BSZ : 0);
#pragma unroll
        for (int i = 0; i < NA4; i++) {
            const int r = ar + i * 32;
            float4 h4, l4;
            h4.x = tf32_rna(pa[i].x); h4.y = tf32_rna(pa[i].y);
            h4.z = tf32_rna(pa[i].z); h4.w = tf32_rna(pa[i].w);
            *(float4*)&Ah[r * BKP + ac] = h4;
            if (SPLIT) {
                l4.x = tf32_rna(pa[i].x - h4.x); l4.y = tf32_rna(pa[i].y - h4.y);
                l4.z = tf32_rna(pa[i].z - h4.z); l4.w = tf32_rna(pa[i].w - h4.w);
                *(float4*)&Al[r * BKP + ac] = l4;
            }
        }
#pragma unroll
        for (int i = 0; i < NB4; i++) {
            const int r = ar + i * 32;
            float4 h4, l4;
            h4.x = tf32_rna(pb[i].x); h4.y = tf32_rna(pb[i].y);
            h4.z = tf32_rna(pb[i].z); h4.w = tf32_rna(pb[i].w);
            *(float4*)&Bh[r * BKP + ac] = h4;
            if (SPLIT) {
                l4.x = tf32_rna(pb[i].x - h4.x); l4.y = tf32_rna(pb[i].y - h4.y);
                l4.z = tf32_rna(pb[i].z - h4.z); l4.w = tf32_rna(pb[i].w - h4.w);
                *(float4*)&Bl[r * BKP + ac] = l4;
            }
        }
    };
    auto compute = [&](int buf) {
        const uint32_t* Ahu = (const uint32_t*)(sm + buf * BUFF);
        const uint32_t* Alu = Ahu + ASZ;             // valid only if SPLIT
        const uint32_t* Bhu = Ahu + NPART * ASZ;
        const uint32_t* Blu = Bhu + BSZ;
#pragma unroll
        for (int ks = 0; ks < 4; ks++) {
            uint32_t bh[WN][2], bl[WN][2];
#pragma unroll
            for (int nt = 0; nt < WN; nt++) {
                const int base = (warp_n0 + nt * 8 + gid) * BKP + ks * 8 + tig;
                bh[nt][0] = Bhu[base]; bh[nt][1] = Bhu[base + 4];
                if (SPLIT) { bl[nt][0] = Blu[base]; bl[nt][1] = Blu[base + 4]; }
            }
#pragma unroll
            for (int mt = 0; mt < WM; mt++) {
                const int base = (warp_m0 + mt * 16 + gid) * BKP + ks * 8 + tig;
                uint32_t ah[4], al[4];
                ah[0] = Ahu[base];           ah[1] = Ahu[base + 8 * BKP];
                ah[2] = Ahu[base + 4];       ah[3] = Ahu[base + 8 * BKP + 4];
                if (SPLIT) {
                    al[0] = Alu[base];       al[1] = Alu[base + 8 * BKP];
                    al[2] = Alu[base + 4];   al[3] = Alu[base + 8 * BKP + 4];
                }
#pragma unroll
                for (int nt = 0; nt < WN; nt++) {
                    MMA_TF32(acc[mt][nt], ah, bh[nt]);
                    if (SPLIT) {
                        MMA_TF32(acc[mt][nt], ah, bl[nt]);
                        MMA_TF32(acc[mt][nt], al, bh[nt]);
                    }
                }
            }
        }
    };

    const int NC = K / 32;
    if (DB == 1) {
        loadA(0); loadB(0);
        for (int c = 0; c < NC; c++) {
            __syncthreads();
            stage(0);
            __syncthreads();
            if (c + 1 < NC) { loadA((c + 1) * 32); loadB((c + 1) * 32); }
            compute(0);
        }
    } else {
        loadA(0); loadB(0);
        stage(0);
        __syncthreads();
        for (int c = 0; c < NC; c++) {
            if (c + 1 < NC) { loadA((c + 1) * 32); loadB((c + 1) * 32); }
            compute(c & 1);
            if (c + 1 < NC) stage((c + 1) & 1);
            __syncthreads();
        }
    }

    // ---------------- epilogue ----------------
#pragma unroll
    for (int mt = 0; mt < WM; mt++) {
#pragma unroll
        for (int nt = 0; nt < WN; nt++) {
            const int m = m0 + warp_m0 + mt * 16 + gid;
            const int n = n0 + warp_n0 + nt * 8 + tig * 2;
            const float* cc = acc[mt][nt];
            if (MODE == 0) {
                // out[((b*H+h)*T+t)*64 + d]
#pragma unroll
                for (int r = 0; r < 2; r++) {
                    const int mm = m + r * 8;
                    const int bb = mm >> 11, t = mm & (T_ - 1);
                    const int h = n >> 6, d0 = n & 63;
                    float2 f; f.x = cc[r * 2]; f.y = cc[r * 2 + 1];
                    *(float2*)&Cout[(((long long)(bb * H_ + h) * T_ + t) * D_) + d0] = f;
                }
            } else if (MODE == 4) {
                // out[((b*H+h)*64+d)*T + t]   (V transposed)
#pragma unroll
                for (int r = 0; r < 2; r++) {
                    const int mm = m + r * 8;
                    const int bb = mm >> 11, t = mm & (T_ - 1);
#pragma unroll
                    for (int jj = 0; jj < 2; jj++) {
                        const int nn = n + jj;
                        const int h = nn >> 6, d0 = nn & 63;
                        Cout[(((long long)(bb * H_ + h) * D_ + d0) * T_) + t] = cc[r * 2 + jj];
                    }
                }
            } else if (MODE == 1) {
#pragma unroll
                for (int r = 0; r < 2; r++) {
                    float2 f; f.x = cc[r * 2] * 8.0f; f.y = cc[r * 2 + 1] * 8.0f;
                    __stcs((float2*)&Cout[(long long)z * T_ * T_ + (long long)(m + r * 8) * T_ + n], f);
                }
            } else if (MODE == 2) {
                const int bb = z >> 4, h = z & 15;
#pragma unroll
                for (int r = 0; r < 2; r++) {
                    float2 f; f.x = cc[r * 2]; f.y = cc[r * 2 + 1];
                    *(float2*)&Cout[((long long)(bb * T_ + m + r * 8)) * C_ + h * D_ + n] = f;
                }
            } else {
#pragma unroll
                for (int r = 0; r < 2; r++) {
                    float2 f;
                    f.x = cc[r * 2]     + bias[n];
                    f.y = cc[r * 2 + 1] + bias[n + 1];
                    *(float2*)&Cout[(long long)(m + r * 8) * C_ + n] = f;
                }
            }
        }
    }
}

// ---------------------------------------------------------------------------
// Head-axis softmax (reference quirk: softmax over dim=1 == H).
// Streaming loads/stores: S is 537 MB, no L2 reuse worth keeping.
// ---------------------------------------------------------------------------
__global__ __launch_bounds__(256) void softmax_head_kernel(float* __restrict__ s)
{
    const long long idx = (long long)blockIdx.x * blockDim.x + threadIdx.x;
    const long long hs = (long long)T_ * T_;
    const int kk = (int)(idx & (T_ - 1));
    const long long bq = idx >> 11;
    const int b = (int)(bq >> 11);
    const int q = (int)(bq & (T_ - 1));
    const long long base = (((long long)b * H_) * T_ + q) * T_ + kk;

    float v[H_];
    float mx = -1e30f;
#pragma unroll
    for (int h = 0; h < H_; h++) {
        v[h] = __ldcs(&s[base + (long long)h * hs]);
        mx = fmaxf(mx, v[h]);
    }
    float sum = 0.0f;
#pragma unroll
    for (int h = 0; h < H_; h++) {
        v[h] = __expf(v[h] - mx);
        sum += v[h];
    }
    const float inv = 1.0f / sum;
#pragma unroll
    for (int h = 0; h < H_; h++)
        __stcs(&s[base + (long long)h * hs], v[h] * inv);
}

// ---------------------------------------------------------------------------
extern "C" void kernel_launch(void* const* d_in, const int* in_sizes, int n_in,
                              void* d_out, int out_size)
{
    const float* query_src = (const float*)d_in[0];
    const float* key_src   = (const float*)d_in[1];
    const float* value_src = (const float*)d_in[2];
    const float* Wq        = (const float*)d_in[3];
    const float* Wk        = (const float*)d_in[4];
    const float* Wv        = (const float*)d_in[5];
    const float* Wo        = (const float*)d_in[6];
    const float* bo        = (const float*)d_in[7];
    float* out = (float*)d_out;

    float *q, *k, *v, *s, *o;
    cudaGetSymbolAddress((void**)&q, g_q);
    cudaGetSymbolAddress((void**)&k, g_k);
    cudaGetSymbolAddress((void**)&v, g_v);
    cudaGetSymbolAddress((void**)&s, g_s);
    cudaGetSymbolAddress((void**)&o, g_o);

    // smem bytes: DB * NPART * (128 + BN) * 36 * 4
    const int SM_SPLIT128   = 2 * (128 + 128) * 36 * 4;       // 73728 (DB=1, split)
    const int SM_SINGLE128D = 2 * (128 + 128) * 36 * 4;       // 73728 (DB=2, single)
    const int SM_SINGLE64D  = 2 * (128 + 64) * 36 * 4;        // 55296 (DB=2, single)
    cudaFuncSetAttribute(mma_gemm<0, true, 128, 1>, cudaFuncAttributeMaxDynamicSharedMemorySize, SM_SPLIT128);
    cudaFuncSetAttribute(mma_gemm<4, false, 128, 2>, cudaFuncAttributeMaxDynamicSharedMemorySize, SM_SINGLE128D);
    cudaFuncSetAttribute(mma_gemm<1, true, 128, 1>, cudaFuncAttributeMaxDynamicSharedMemorySize, SM_SPLIT128);
    cudaFuncSetAttribute(mma_gemm<2, false, 64, 2>, cudaFuncAttributeMaxDynamicSharedMemorySize, SM_SINGLE64D);
    cudaFuncSetAttribute(mma_gemm<3, false, 128, 2>, cudaFuncAttributeMaxDynamicSharedMemorySize, SM_SINGLE128D);

    const dim3 blk(256);

    // Pass 1: projections y = x @ W^T.  Q,K split -> [b,h,t,d]; V single -> [b,h,d,t]
    {
        dim3 grid(C_ / 128, (B_ * T_) / 128, 1);
        mma_gemm<0, true, 128, 1><<<grid, blk, SM_SPLIT128>>>(query_src, Wq, q, nullptr, C_, C_, C_, 0, 0);
        mma_gemm<0, true, 128, 1><<<grid, blk, SM_SPLIT128>>>(key_src,   Wk, k, nullptr, C_, C_, C_, 0, 0);
        mma_gemm<4, false, 128, 2><<<grid, blk, SM_SINGLE128D>>>(value_src, Wv, v, nullptr, C_, C_, C_, 0, 0);
    }
    // Pass 2: S[b,h,q,k] = 8 * q.k   (split tf32)
    {
        dim3 grid(T_ / 128, T_ / 128, B_ * H_);
        mma_gemm<1, true, 128, 1><<<grid, blk, SM_SPLIT128>>>(q, k, s, nullptr, D_, D_, D_,
                                                              (long long)T_ * D_, (long long)T_ * D_);
    }
    // Pass 3: softmax over HEAD axis (in place)
    {
        const long long total = (long long)B_ * T_ * T_;
        softmax_head_kernel<<<(unsigned)(total / 256), 256>>>(s);
    }
    // Pass 4: O = P @ V^T_stored -> [b][q][h*64+d]   (single tf32, double-buffered)
    {
        dim3 grid(1, T_ / 128, B_ * H_);
        mma_gemm<2, false, 64, 2><<<grid, blk, SM_SINGLE64D>>>(s, v, o, nullptr, T_, T_, T_,
                                                               (long long)T_ * T_, (long long)D_ * T_);
    }
    // Pass 5: out = O @ Wo^T + bo   (single tf32, double-buffered)
    {
        dim3 grid(C_ / 128, (B_ * T_) / 128, 1);
        mma_gemm<3, false, 128, 2><<<grid, blk, SM_SINGLE128D>>>(o, Wo, out, bo, C_, C_, C_, 0, 0);
    }
}

// round 11
// speedup vs baseline: 1.4418x; 1.4418x over previous
#include <cuda_runtime.h>
#include <cstdint>

#define B_ 2
#define T_ 2048
#define C_ 1024
#define H_ 16
#define D_ 64

// ---- scratch (no cudaMalloc allowed) ----
__device__ float g_q[(size_t)B_ * H_ * T_ * D_];          // [b][h][t][d]
__device__ float g_k[(size_t)B_ * H_ * T_ * D_];          // [b][h][t][d]
__device__ float g_v[(size_t)B_ * H_ * D_ * T_];          // [b][h][d][t]  (TRANSPOSED)
__device__ float g_s[(size_t)B_ * H_ * T_ * T_];          // [b][h][q][k]
__device__ float g_o[(size_t)B_ * T_ * C_];               // [b][t][h*64+d]

__device__ __forceinline__ float tf32_rna(float x) {
    float y;
    asm("cvt.rna.tf32.f32 %0, %1;" : "=f"(y) : "f"(x));
    return y;
}

// m16n8k8 tf32 mma (baseline PTX, maps to HMMA on sm_103)
#define MMA_TF32(c, a, b)                                                        \
    asm volatile("mma.sync.aligned.m16n8k8.row.col.f32.tf32.tf32.f32 "           \
                 "{%0,%1,%2,%3}, {%4,%5,%6,%7}, {%8,%9}, {%0,%1,%2,%3};"         \
                 : "+f"((c)[0]), "+f"((c)[1]), "+f"((c)[2]), "+f"((c)[3])        \
                 : "r"((a)[0]), "r"((a)[1]), "r"((a)[2]), "r"((a)[3]),           \
                   "r"((b)[0]), "r"((b)[1]))

// ============================================================================
// Tensor-core GEMM:  C[m,n] = sum_k A[m,k] * B[n,k]   (NT; B row n, col k)
// CTA: 128 x BN x 32, 256 thr (8 warps).
//   BN=128: warps 2m x 4n (warp tile 64x32);  BN=64: warps 4m x 2n (32x32).
// SPLIT: 2-term tf32 split (hi*hi + hi*lo + lo*hi) -> fp32-class accuracy.
// MODE 0: QK proj -> out[((b*H+h)*T+t)*64+d]
// MODE 4: V proj  -> out[((b*H+h)*64+d)*T+t]   (transposed)
// MODE 1: S       -> out[z*T*T + m*T + n] * 8
// MODE 2: PV      -> out[(b*T+m)*C + h*64 + n]
// MODE 3: O proj  -> out[m*C+n] + bias[n]
// ============================================================================
template <int MODE, bool SPLIT, int BN>
__global__ __launch_bounds__(256, 2) void mma_gemm(
    const float* __restrict__ A, const float* __restrict__ Bm,
    float* __restrict__ Cout, const float* __restrict__ bias,
    int K, int lda, int ldb, long long sA, long long sB)
{
    constexpr int BM = 128, BKP = 36;
    constexpr int GM = (BN == 128) ? 2 : 4;       // warp grid (m)
    constexpr int WM = (BN == 128) ? 4 : 2;       // m16 tiles per warp
    constexpr int WN = 4;                         // n8 tiles per warp
    constexpr int NA4 = 4;                        // A float4s per thread per chunk
    constexpr int NB4 = BN / 32;                  // B float4s per thread per chunk
    constexpr int ASZ = BM * BKP;
    constexpr int BSZ = BN * BKP;

    extern __shared__ float sm[];
    float* Ah = sm;
    float* Al = Ah + (SPLIT ? ASZ : 0);
    float* Bh = Ah + (SPLIT ? 2 : 1) * ASZ;
    float* Bl = Bh + (SPLIT ? BSZ : 0);

    const int tid = threadIdx.x;
    const int w   = tid >> 5;
    const int lane = tid & 31;
    const int gid = lane >> 2;     // 0..7
    const int tig = lane & 3;      // 0..3
    const int wm = w % GM;
    const int wn = w / GM;
    const int warp_m0 = wm * WM * 16;
    const int warp_n0 = wn * WN * 8;

    const int z = blockIdx.z;
    const float* Ab = A + (long long)z * sA;
    const float* Bb = Bm + (long long)z * sB;
    const int m0 = blockIdx.y * BM;
    const int n0 = blockIdx.x * BN;

    const int ar = tid >> 3;            // 0..31
    const int ac = (tid & 7) * 4;       // 0,4,...,28

    float acc[WM][WN][4];
#pragma unroll
    for (int i = 0; i < WM; i++)
#pragma unroll
        for (int j = 0; j < WN; j++)
#pragma unroll
            for (int t = 0; t < 4; t++) acc[i][j][t] = 0.0f;

    float4 pa[NA4], pb[NB4];
    auto loadA = [&](int k0) {
#pragma unroll
        for (int i = 0; i < NA4; i++)
            pa[i] = *(const float4*)(Ab + (long long)(m0 + ar + i * 32) * lda + k0 + ac);
    };
    auto loadB = [&](int k0) {
#pragma unroll
        for (int i = 0; i < NB4; i++)
            pb[i] = *(const float4*)(Bb + (long long)(n0 + ar + i * 32) * ldb + k0 + ac);
    };
    auto stage = [&]() {
#pragma unroll
        for (int i = 0; i < NA4; i++) {
            const int r = ar + i * 32;
            float4 h4, l4;
            h4.x = tf32_rna(pa[i].x); h4.y = tf32_rna(pa[i].y);
            h4.z = tf32_rna(pa[i].z); h4.w = tf32_rna(pa[i].w);
            *(float4*)&Ah[r * BKP + ac] = h4;
            if (SPLIT) {
                l4.x = tf32_rna(pa[i].x - h4.x); l4.y = tf32_rna(pa[i].y - h4.y);
                l4.z = tf32_rna(pa[i].z - h4.z); l4.w = tf32_rna(pa[i].w - h4.w);
                *(float4*)&Al[r * BKP + ac] = l4;
            }
        }
#pragma unroll
        for (int i = 0; i < NB4; i++) {
            const int r = ar + i * 32;
            float4 h4, l4;
            h4.x = tf32_rna(pb[i].x); h4.y = tf32_rna(pb[i].y);
            h4.z = tf32_rna(pb[i].z); h4.w = tf32_rna(pb[i].w);
            *(float4*)&Bh[r * BKP + ac] = h4;
            if (SPLIT) {
                l4.x = tf32_rna(pb[i].x - h4.x); l4.y = tf32_rna(pb[i].y - h4.y);
                l4.z = tf32_rna(pb[i].z - h4.z); l4.w = tf32_rna(pb[i].w - h4.w);
                *(float4*)&Bl[r * BKP + ac] = l4;
            }
        }
    };

    const uint32_t* Ahu = (const uint32_t*)Ah;
    const uint32_t* Alu = (const uint32_t*)Al;
    const uint32_t* Bhu = (const uint32_t*)Bh;
    const uint32_t* Blu = (const uint32_t*)Bl;

    const int NC = K / 32;
    loadA(0); loadB(0);
    for (int c = 0; c < NC; c++) {
        __syncthreads();                 // previous compute done (no-op on c=0)
        stage();
        __syncthreads();
        if (c + 1 < NC) { loadA((c + 1) * 32); loadB((c + 1) * 32); }

#pragma unroll
        for (int ks = 0; ks < 4; ks++) {
            uint32_t bh[WN][2], bl[WN][2];
#pragma unroll
            for (int nt = 0; nt < WN; nt++) {
                const int base = (warp_n0 + nt * 8 + gid) * BKP + ks * 8 + tig;
                bh[nt][0] = Bhu[base]; bh[nt][1] = Bhu[base + 4];
                if (SPLIT) { bl[nt][0] = Blu[base]; bl[nt][1] = Blu[base + 4]; }
            }
#pragma unroll
            for (int mt = 0; mt < WM; mt++) {
                const int base = (warp_m0 + mt * 16 + gid) * BKP + ks * 8 + tig;
                uint32_t ah[4], al[4];
                ah[0] = Ahu[base];           ah[1] = Ahu[base + 8 * BKP];
                ah[2] = Ahu[base + 4];       ah[3] = Ahu[base + 8 * BKP + 4];
                if (SPLIT) {
                    al[0] = Alu[base];       al[1] = Alu[base + 8 * BKP];
                    al[2] = Alu[base + 4];   al[3] = Alu[base + 8 * BKP + 4];
                }
#pragma unroll
                for (int nt = 0; nt < WN; nt++) {
                    MMA_TF32(acc[mt][nt], ah, bh[nt]);
                    if (SPLIT) {
                        MMA_TF32(acc[mt][nt], ah, bl[nt]);
                        MMA_TF32(acc[mt][nt], al, bh[nt]);
                    }
                }
            }
        }
    }

    // ---------------- epilogue ----------------
#pragma unroll
    for (int mt = 0; mt < WM; mt++) {
#pragma unroll
        for (int nt = 0; nt < WN; nt++) {
            const int m = m0 + warp_m0 + mt * 16 + gid;
            const int n = n0 + warp_n0 + nt * 8 + tig * 2;
            const float* cc = acc[mt][nt];
            if (MODE == 0) {
                // out[((b*H+h)*T+t)*64 + d]
#pragma unroll
                for (int r = 0; r < 2; r++) {
                    const int mm = m + r * 8;
                    const int bb = mm >> 11, t = mm & (T_ - 1);
                    const int h = n >> 6, d0 = n & 63;
                    float2 f; f.x = cc[r * 2]; f.y = cc[r * 2 + 1];
                    *(float2*)&Cout[(((long long)(bb * H_ + h) * T_ + t) * D_) + d0] = f;
                }
            } else if (MODE == 4) {
                // out[((b*H+h)*64+d)*T + t]   (V transposed)
#pragma unroll
                for (int r = 0; r < 2; r++) {
                    const int mm = m + r * 8;
                    const int bb = mm >> 11, t = mm & (T_ - 1);
#pragma unroll
                    for (int jj = 0; jj < 2; jj++) {
                        const int nn = n + jj;
                        const int h = nn >> 6, d0 = nn & 63;
                        Cout[(((long long)(bb * H_ + h) * D_ + d0) * T_) + t] = cc[r * 2 + jj];
                    }
                }
            } else if (MODE == 1) {
#pragma unroll
                for (int r = 0; r < 2; r++) {
                    float2 f; f.x = cc[r * 2] * 8.0f; f.y = cc[r * 2 + 1] * 8.0f;
                    *(float2*)&Cout[(long long)z * T_ * T_ + (long long)(m + r * 8) * T_ + n] = f;
                }
            } else if (MODE == 2) {
                const int bb = z >> 4, h = z & 15;
#pragma unroll
                for (int r = 0; r < 2; r++) {
                    float2 f; f.x = cc[r * 2]; f.y = cc[r * 2 + 1];
                    *(float2*)&Cout[((long long)(bb * T_ + m + r * 8)) * C_ + h * D_ + n] = f;
                }
            } else {
#pragma unroll
                for (int r = 0; r < 2; r++) {
                    float2 f;
                    f.x = cc[r * 2]     + bias[n];
                    f.y = cc[r * 2 + 1] + bias[n + 1];
                    *(float2*)&Cout[(long long)(m + r * 8) * C_ + n] = f;
                }
            }
        }
    }
}

// ---------------------------------------------------------------------------
// Head-axis softmax (reference quirk: softmax over dim=1 == H).
// ---------------------------------------------------------------------------
__global__ __launch_bounds__(256) void softmax_head_kernel(float* __restrict__ s)
{
    const long long idx = (long long)blockIdx.x * blockDim.x + threadIdx.x;
    const long long hs = (long long)T_ * T_;
    const int kk = (int)(idx & (T_ - 1));
    const long long bq = idx >> 11;
    const int b = (int)(bq >> 11);
    const int q = (int)(bq & (T_ - 1));
    const long long base = (((long long)b * H_) * T_ + q) * T_ + kk;

    float v[H_];
    float mx = -1e30f;
#pragma unroll
    for (int h = 0; h < H_; h++) {
        v[h] = s[base + (long long)h * hs];
        mx = fmaxf(mx, v[h]);
    }
    float sum = 0.0f;
#pragma unroll
    for (int h = 0; h < H_; h++) {
        v[h] = __expf(v[h] - mx);
        sum += v[h];
    }
    const float inv = 1.0f / sum;
#pragma unroll
    for (int h = 0; h < H_; h++)
        s[base + (long long)h * hs] = v[h] * inv;
}

// ---------------------------------------------------------------------------
extern "C" void kernel_launch(void* const* d_in, const int* in_sizes, int n_in,
                              void* d_out, int out_size)
{
    const float* query_src = (const float*)d_in[0];
    const float* key_src   = (const float*)d_in[1];
    const float* value_src = (const float*)d_in[2];
    const float* Wq        = (const float*)d_in[3];
    const float* Wk        = (const float*)d_in[4];
    const float* Wv        = (const float*)d_in[5];
    const float* Wo        = (const float*)d_in[6];
    const float* bo        = (const float*)d_in[7];
    float* out = (float*)d_out;

    float *q, *k, *v, *s, *o;
    cudaGetSymbolAddress((void**)&q, g_q);
    cudaGetSymbolAddress((void**)&k, g_k);
    cudaGetSymbolAddress((void**)&v, g_v);
    cudaGetSymbolAddress((void**)&s, g_s);
    cudaGetSymbolAddress((void**)&o, g_o);

    // smem sizes: (A parts + B parts) * BKP(36) * 4B
    const int SM_SPLIT128  = (2 * 128 + 2 * 128) * 36 * 4;  // 73728
    const int SM_SINGLE128 = (128 + 128) * 36 * 4;          // 36864
    const int SM_SINGLE64  = (128 + 64) * 36 * 4;           // 27648
    cudaFuncSetAttribute(mma_gemm<0, true, 128>, cudaFuncAttributeMaxDynamicSharedMemorySize, SM_SPLIT128);
    cudaFuncSetAttribute(mma_gemm<4, false, 128>, cudaFuncAttributeMaxDynamicSharedMemorySize, SM_SINGLE128);
    cudaFuncSetAttribute(mma_gemm<1, true, 128>, cudaFuncAttributeMaxDynamicSharedMemorySize, SM_SPLIT128);
    cudaFuncSetAttribute(mma_gemm<2, false, 64>, cudaFuncAttributeMaxDynamicSharedMemorySize, SM_SINGLE64);
    cudaFuncSetAttribute(mma_gemm<3, false, 128>, cudaFuncAttributeMaxDynamicSharedMemorySize, SM_SINGLE128);

    const dim3 blk(256);

    // Pass 1: projections y = x @ W^T.  Q,K split -> [b,h,t,d]; V single -> [b,h,d,t]
    {
        dim3 grid(C_ / 128, (B_ * T_) / 128, 1);
        mma_gemm<0, true, 128><<<grid, blk, SM_SPLIT128>>>(query_src, Wq, q, nullptr, C_, C_, C_, 0, 0);
        mma_gemm<0, true, 128><<<grid, blk, SM_SPLIT128>>>(key_src,   Wk, k, nullptr, C_, C_, C_, 0, 0);
        mma_gemm<4, false, 128><<<grid, blk, SM_SINGLE128>>>(value_src, Wv, v, nullptr, C_, C_, C_, 0, 0);
    }
    // Pass 2: S[b,h,q,k] = 8 * q.k   (split tf32)
    {
        dim3 grid(T_ / 128, T_ / 128, B_ * H_);
        mma_gemm<1, true, 128><<<grid, blk, SM_SPLIT128>>>(q, k, s, nullptr, D_, D_, D_,
                                                           (long long)T_ * D_, (long long)T_ * D_);
    }
    // Pass 3: softmax over HEAD axis (in place)
    {
        const long long total = (long long)B_ * T_ * T_;
        softmax_head_kernel<<<(unsigned)(total / 256), 256>>>(s);
    }
    // Pass 4: O = P @ V^T_stored -> [b][q][h*64+d]   (single tf32, NT vs transposed V)
    {
        dim3 grid(1, T_ / 128, B_ * H_);
        mma_gemm<2, false, 64><<<grid, blk, SM_SINGLE64>>>(s, v, o, nullptr, T_, T_, T_,
                                                           (long long)T_ * T_, (long long)D_ * T_);
    }
    // Pass 5: out = O @ Wo^T + bo   (single tf32)
    {
        dim3 grid(C_ / 128, (B_ * T_) / 128, 1);
        mma_gemm<3, false, 128><<<grid, blk, SM_SINGLE128>>>(o, Wo, out, bo, C_, C_, C_, 0, 0);
    }
}

// round 12
// speedup vs baseline: 1.5305x; 1.0615x over previous
#include <cuda_runtime.h>
#include <cstdint>

#define B_ 2
#define T_ 2048
#define C_ 1024
#define H_ 16
#define D_ 64

// ---- scratch (no cudaMalloc allowed) ----
__device__ float g_q[(size_t)B_ * H_ * T_ * D_];          // [b][h][t][d]
__device__ float g_k[(size_t)B_ * H_ * T_ * D_];          // [b][h][t][d]
__device__ float g_v[(size_t)B_ * H_ * D_ * T_];          // [b][h][d][t]  (TRANSPOSED)
__device__ float g_s[(size_t)B_ * H_ * T_ * T_];          // [b][h][q][k]
__device__ float g_o[(size_t)B_ * T_ * C_];               // [b][t][h*64+d]

__device__ __forceinline__ float tf32_rna(float x) {
    float y;
    asm("cvt.rna.tf32.f32 %0, %1;" : "=f"(y) : "f"(x));
    return y;
}
__device__ __forceinline__ uint32_t smem_u32(const void* p) {
    uint32_t a;
    asm("{ .reg .u64 t; cvta.to.shared.u64 t, %1; cvt.u32.u64 %0, t; }" : "=r"(a) : "l"(p));
    return a;
}

// m16n8k8 tf32 mma (baseline PTX, maps to HMMA on sm_103)
#define MMA_TF32(c, a, b)                                                        \
    asm volatile("mma.sync.aligned.m16n8k8.row.col.f32.tf32.tf32.f32 "           \
                 "{%0,%1,%2,%3}, {%4,%5,%6,%7}, {%8,%9}, {%0,%1,%2,%3};"         \
                 : "+f"((c)[0]), "+f"((c)[1]), "+f"((c)[2]), "+f"((c)[3])        \
                 : "r"((a)[0]), "r"((a)[1]), "r"((a)[2]), "r"((a)[3]),           \
                   "r"((b)[0]), "r"((b)[1]))

// ldmatrix: tf32 fragments via b16 tiles (baseline PTX, sm_75+)
#define LDSM_X4(r, a)                                                            \
    asm volatile("ldmatrix.sync.aligned.m8n8.x4.shared.b16 {%0,%1,%2,%3}, [%4];" \
                 : "=r"((r)[0]), "=r"((r)[1]), "=r"((r)[2]), "=r"((r)[3])        \
                 : "r"(a))
#define LDSM_X2(r, a)                                                            \
    asm volatile("ldmatrix.sync.aligned.m8n8.x2.shared.b16 {%0,%1}, [%2];"       \
                 : "=r"((r)[0]), "=r"((r)[1])                                    \
                 : "r"(a))

// ============================================================================
// Tensor-core GEMM:  C[m,n] = sum_k A[m,k] * B[n,k]   (NT; B row n, col k)
// CTA: 128 x BN x 32, 256 thr (8 warps).
//   BN=128: warps 2m x 4n (warp tile 64x32);  BN=64: warps 4m x 2n (32x32).
// SPLIT: 2-term tf32 split (hi*hi + hi*lo + lo*hi) -> fp32-class accuracy.
// Fragment loads via ldmatrix (1 LDSM.x4 per A frag, 1 LDSM.x2 per B frag).
// MODE 0: QK proj -> out[((b*H+h)*T+t)*64+d]
// MODE 4: V proj  -> out[((b*H+h)*64+d)*T+t]   (transposed)
// MODE 1: S       -> out[z*T*T + m*T + n] * 8
// MODE 2: PV      -> out[(b*T+m)*C + h*64 + n]
// MODE 3: O proj  -> out[m*C+n] + bias[n]
// ============================================================================
template <int MODE, bool SPLIT, int BN>
__global__ __launch_bounds__(256, 2) void mma_gemm(
    const float* __restrict__ A, const float* __restrict__ Bm,
    float* __restrict__ Cout, const float* __restrict__ bias,
    int K, int lda, int ldb, long long sA, long long sB)
{
    constexpr int BM = 128, BKP = 36;
    constexpr int GM = (BN == 128) ? 2 : 4;       // warp grid (m)
    constexpr int WM = (BN == 128) ? 4 : 2;       // m16 tiles per warp
    constexpr int WN = 4;                         // n8 tiles per warp
    constexpr int NA4 = 4;                        // A float4s per thread per chunk
    constexpr int NB4 = BN / 32;                  // B float4s per thread per chunk
    constexpr int ASZ = BM * BKP;
    constexpr int BSZ = BN * BKP;

    extern __shared__ float sm[];
    float* Ah = sm;
    float* Al = Ah + (SPLIT ? ASZ : 0);
    float* Bh = Ah + (SPLIT ? 2 : 1) * ASZ;
    float* Bl = Bh + (SPLIT ? BSZ : 0);

    const int tid = threadIdx.x;
    const int w   = tid >> 5;
    const int lane = tid & 31;
    const int gid = lane >> 2;     // 0..7
    const int tig = lane & 3;      // 0..3
    const int wm = w % GM;
    const int wn = w / GM;
    const int warp_m0 = wm * WM * 16;
    const int warp_n0 = wn * WN * 8;

    const int z = blockIdx.z;
    const float* Ab = A + (long long)z * sA;
    const float* Bb = Bm + (long long)z * sB;
    const int m0 = blockIdx.y * BM;
    const int n0 = blockIdx.x * BN;

    const int ar = tid >> 3;            // 0..31
    const int ac = (tid & 7) * 4;       // 0,4,...,28

    // ---- ldmatrix per-lane base addresses (bytes into smem) ----
    // A x4 tiles: m0..3 = (rows 0-7 / 8-15) x (k 0-3 / 4-7)
    const int a_row = warp_m0 + (lane & 7) + ((lane >> 3) & 1) * 8;
    const int a_col = (lane >> 4) * 4;
    const uint32_t sAh = smem_u32(Ah) + (uint32_t)((a_row * BKP + a_col) * 4);
    const uint32_t sAl = sAh + (SPLIT ? ASZ * 4 : 0);
    // B x2 tiles: n rows 0-7 x (k 0-3 / 4-7); lanes 16-31 mirror 0-15
    const int b_lane = lane & 15;
    const int b_row = warp_n0 + (b_lane & 7);
    const int b_col = ((b_lane >> 3) & 1) * 4;
    const uint32_t sBh = smem_u32(Bh) + (uint32_t)((b_row * BKP + b_col) * 4);
    const uint32_t sBl = sBh + (SPLIT ? BSZ * 4 : 0);

    float acc[WM][WN][4];
#pragma unroll
    for (int i = 0; i < WM; i++)
#pragma unroll
        for (int j = 0; j < WN; j++)
#pragma unroll
            for (int t = 0; t < 4; t++) acc[i][j][t] = 0.0f;

    float4 pa[NA4], pb[NB4];
    auto loadA = [&](int k0) {
#pragma unroll
        for (int i = 0; i < NA4; i++)
            pa[i] = *(const float4*)(Ab + (long long)(m0 + ar + i * 32) * lda + k0 + ac);
    };
    auto loadB = [&](int k0) {
#pragma unroll
        for (int i = 0; i < NB4; i++)
            pb[i] = *(const float4*)(Bb + (long long)(n0 + ar + i * 32) * ldb + k0 + ac);
    };
    auto stage = [&]() {
#pragma unroll
        for (int i = 0; i < NA4; i++) {
            const int r = ar + i * 32;
            float4 h4, l4;
            h4.x = tf32_rna(pa[i].x); h4.y = tf32_rna(pa[i].y);
            h4.z = tf32_rna(pa[i].z); h4.w = tf32_rna(pa[i].w);
            *(float4*)&Ah[r * BKP + ac] = h4;
            if (SPLIT) {
                l4.x = tf32_rna(pa[i].x - h4.x); l4.y = tf32_rna(pa[i].y - h4.y);
                l4.z = tf32_rna(pa[i].z - h4.z); l4.w = tf32_rna(pa[i].w - h4.w);
                *(float4*)&Al[r * BKP + ac] = l4;
            }
        }
#pragma unroll
        for (int i = 0; i < NB4; i++) {
            const int r = ar + i * 32;
            float4 h4, l4;
            h4.x = tf32_rna(pb[i].x); h4.y = tf32_rna(pb[i].y);
            h4.z = tf32_rna(pb[i].z); h4.w = tf32_rna(pb[i].w);
            *(float4*)&Bh[r * BKP + ac] = h4;
            if (SPLIT) {
                l4.x = tf32_rna(pb[i].x - h4.x); l4.y = tf32_rna(pb[i].y - h4.y);
                l4.z = tf32_rna(pb[i].z - h4.z); l4.w = tf32_rna(pb[i].w - h4.w);
                *(float4*)&Bl[r * BKP + ac] = l4;
            }
        }
    };

    const int NC = K / 32;
    loadA(0); loadB(0);
    for (int c = 0; c < NC; c++) {
        __syncthreads();                 // previous compute done (no-op on c=0)
        stage();
        __syncthreads();
        if (c + 1 < NC) { loadA((c + 1) * 32); loadB((c + 1) * 32); }

#pragma unroll
        for (int ks = 0; ks < 4; ks++) {
            uint32_t bh[WN][2], bl[WN][2];
#pragma unroll
            for (int nt = 0; nt < WN; nt++) {
                const uint32_t off = (uint32_t)((nt * 8 * BKP + ks * 8) * 4);
                LDSM_X2(bh[nt], sBh + off);
                if (SPLIT) LDSM_X2(bl[nt], sBl + off);
            }
#pragma unroll
            for (int mt = 0; mt < WM; mt++) {
                const uint32_t off = (uint32_t)((mt * 16 * BKP + ks * 8) * 4);
                uint32_t ah[4], al[4];
                LDSM_X4(ah, sAh + off);
                if (SPLIT) LDSM_X4(al, sAl + off);
#pragma unroll
                for (int nt = 0; nt < WN; nt++) {
                    MMA_TF32(acc[mt][nt], ah, bh[nt]);
                    if (SPLIT) {
                        MMA_TF32(acc[mt][nt], ah, bl[nt]);
                        MMA_TF32(acc[mt][nt], al, bh[nt]);
                    }
                }
            }
        }
    }

    // ---------------- epilogue ----------------
#pragma unroll
    for (int mt = 0; mt < WM; mt++) {
#pragma unroll
        for (int nt = 0; nt < WN; nt++) {
            const int m = m0 + warp_m0 + mt * 16 + gid;
            const int n = n0 + warp_n0 + nt * 8 + tig * 2;
            const float* cc = acc[mt][nt];
            if (MODE == 0) {
                // out[((b*H+h)*T+t)*64 + d]
#pragma unroll
                for (int r = 0; r < 2; r++) {
                    const int mm = m + r * 8;
                    const int bb = mm >> 11, t = mm & (T_ - 1);
                    const int h = n >> 6, d0 = n & 63;
                    float2 f; f.x = cc[r * 2]; f.y = cc[r * 2 + 1];
                    *(float2*)&Cout[(((long long)(bb * H_ + h) * T_ + t) * D_) + d0] = f;
                }
            } else if (MODE == 4) {
                // out[((b*H+h)*64+d)*T + t]   (V transposed)
#pragma unroll
                for (int r = 0; r < 2; r++) {
                    const int mm = m + r * 8;
                    const int bb = mm >> 11, t = mm & (T_ - 1);
#pragma unroll
                    for (int jj = 0; jj < 2; jj++) {
                        const int nn = n + jj;
                        const int h = nn >> 6, d0 = nn & 63;
                        Cout[(((long long)(bb * H_ + h) * D_ + d0) * T_) + t] = cc[r * 2 + jj];
                    }
                }
            } else if (MODE == 1) {
#pragma unroll
                for (int r = 0; r < 2; r++) {
                    float2 f; f.x = cc[r * 2] * 8.0f; f.y = cc[r * 2 + 1] * 8.0f;
                    *(float2*)&Cout[(long long)z * T_ * T_ + (long long)(m + r * 8) * T_ + n] = f;
                }
            } else if (MODE == 2) {
                const int bb = z >> 4, h = z & 15;
#pragma unroll
                for (int r = 0; r < 2; r++) {
                    float2 f; f.x = cc[r * 2]; f.y = cc[r * 2 + 1];
                    *(float2*)&Cout[((long long)(bb * T_ + m + r * 8)) * C_ + h * D_ + n] = f;
                }
            } else {
#pragma unroll
                for (int r = 0; r < 2; r++) {
                    float2 f;
                    f.x = cc[r * 2]     + bias[n];
                    f.y = cc[r * 2 + 1] + bias[n + 1];
                    *(float2*)&Cout[(long long)(m + r * 8) * C_ + n] = f;
                }
            }
        }
    }
}

// ---------------------------------------------------------------------------
// Head-axis softmax (reference quirk: softmax over dim=1 == H).
// Vectorized: each thread handles 4 consecutive k (float4 per head).
// ---------------------------------------------------------------------------
__global__ __launch_bounds__(256) void softmax_head_kernel(float* __restrict__ s)
{
    const long long idx = (long long)blockIdx.x * blockDim.x + threadIdx.x; // over B*T*(T/4)
    const long long hs = (long long)T_ * T_;
    const int k4 = (int)(idx & (T_ / 4 - 1)) * 4;
    const long long bq = idx >> 9;            // b*T + q
    const int b = (int)(bq >> 11);
    const int q = (int)(bq & (T_ - 1));
    const long long base = (((long long)b * H_) * T_ + q) * T_ + k4;

    float4 v[H_];
    float4 mx = make_float4(-1e30f, -1e30f, -1e30f, -1e30f);
#pragma unroll
    for (int h = 0; h < H_; h++) {
        v[h] = *(const float4*)&s[base + (long long)h * hs];
        mx.x = fmaxf(mx.x, v[h].x); mx.y = fmaxf(mx.y, v[h].y);
        mx.z = fmaxf(mx.z, v[h].z); mx.w = fmaxf(mx.w, v[h].w);
    }
    float4 sum = make_float4(0.f, 0.f, 0.f, 0.f);
#pragma unroll
    for (int h = 0; h < H_; h++) {
        v[h].x = __expf(v[h].x - mx.x); v[h].y = __expf(v[h].y - mx.y);
        v[h].z = __expf(v[h].z - mx.z); v[h].w = __expf(v[h].w - mx.w);
        sum.x += v[h].x; sum.y += v[h].y; sum.z += v[h].z; sum.w += v[h].w;
    }
    const float ix = 1.0f / sum.x, iy = 1.0f / sum.y;
    const float iz = 1.0f / sum.z, iw = 1.0f / sum.w;
#pragma unroll
    for (int h = 0; h < H_; h++) {
        float4 f;
        f.x = v[h].x * ix; f.y = v[h].y * iy;
        f.z = v[h].z * iz; f.w = v[h].w * iw;
        *(float4*)&s[base + (long long)h * hs] = f;
    }
}

// ---------------------------------------------------------------------------
extern "C" void kernel_launch(void* const* d_in, const int* in_sizes, int n_in,
                              void* d_out, int out_size)
{
    const float* query_src = (const float*)d_in[0];
    const float* key_src   = (const float*)d_in[1];
    const float* value_src = (const float*)d_in[2];
    const float* Wq        = (const float*)d_in[3];
    const float* Wk        = (const float*)d_in[4];
    const float* Wv        = (const float*)d_in[5];
    const float* Wo        = (const float*)d_in[6];
    const float* bo        = (const float*)d_in[7];
    float* out = (float*)d_out;

    float *q, *k, *v, *s, *o;
    cudaGetSymbolAddress((void**)&q, g_q);
    cudaGetSymbolAddress((void**)&k, g_k);
    cudaGetSymbolAddress((void**)&v, g_v);
    cudaGetSymbolAddress((void**)&s, g_s);
    cudaGetSymbolAddress((void**)&o, g_o);

    // smem sizes: (A parts + B parts) * BKP(36) * 4B
    const int SM_SPLIT128  = (2 * 128 + 2 * 128) * 36 * 4;  // 73728
    const int SM_SINGLE128 = (128 + 128) * 36 * 4;          // 36864
    const int SM_SINGLE64  = (128 + 64) * 36 * 4;           // 27648
    cudaFuncSetAttribute(mma_gemm<0, true, 128>, cudaFuncAttributeMaxDynamicSharedMemorySize, SM_SPLIT128);
    cudaFuncSetAttribute(mma_gemm<4, false, 128>, cudaFuncAttributeMaxDynamicSharedMemorySize, SM_SINGLE128);
    cudaFuncSetAttribute(mma_gemm<1, true, 128>, cudaFuncAttributeMaxDynamicSharedMemorySize, SM_SPLIT128);
    cudaFuncSetAttribute(mma_gemm<2, false, 64>, cudaFuncAttributeMaxDynamicSharedMemorySize, SM_SINGLE64);
    cudaFuncSetAttribute(mma_gemm<3, false, 128>, cudaFuncAttributeMaxDynamicSharedMemorySize, SM_SINGLE128);

    const dim3 blk(256);

    // Pass 1: projections y = x @ W^T.  Q,K split -> [b,h,t,d]; V single -> [b,h,d,t]
    {
        dim3 grid(C_ / 128, (B_ * T_) / 128, 1);
        mma_gemm<0, true, 128><<<grid, blk, SM_SPLIT128>>>(query_src, Wq, q, nullptr, C_, C_, C_, 0, 0);
        mma_gemm<0, true, 128><<<grid, blk, SM_SPLIT128>>>(key_src,   Wk, k, nullptr, C_, C_, C_, 0, 0);
        mma_gemm<4, false, 128><<<grid, blk, SM_SINGLE128>>>(value_src, Wv, v, nullptr, C_, C_, C_, 0, 0);
    }
    // Pass 2: S[b,h,q,k] = 8 * q.k   (split tf32)
    {
        dim3 grid(T_ / 128, T_ / 128, B_ * H_);
        mma_gemm<1, true, 128><<<grid, blk, SM_SPLIT128>>>(q, k, s, nullptr, D_, D_, D_,
                                                           (long long)T_ * D_, (long long)T_ * D_);
    }
    // Pass 3: softmax over HEAD axis (in place, vectorized over k)
    {
        const long long total = (long long)B_ * T_ * (T_ / 4);
        softmax_head_kernel<<<(unsigned)(total / 256), 256>>>(s);
    }
    // Pass 4: O = P @ V^T_stored -> [b][q][h*64+d]   (single tf32, NT vs transposed V)
    {
        dim3 grid(1, T_ / 128, B_ * H_);
        mma_gemm<2, false, 64><<<grid, blk, SM_SINGLE64>>>(s, v, o, nullptr, T_, T_, T_,
                                                           (long long)T_ * T_, (long long)D_ * T_);
    }
    // Pass 5: out = O @ Wo^T + bo   (single tf32)
    {
        dim3 grid(C_ / 128, (B_ * T_) / 128, 1);
        mma_gemm<3, false, 128><<<grid, blk, SM_SINGLE128>>>(o, Wo, out, bo, C_, C_, C_, 0, 0);
    }
}

// round 14
// speedup vs baseline: 1.6689x; 1.0904x over previous
#include <cuda_runtime.h>
#include <cuda_fp16.h>
#include <cstdint>

#define B_ 2
#define T_ 2048
#define C_ 1024
#define H_ 16
#define D_ 64

// ---- scratch (no cudaMalloc allowed) ----
__device__ float  g_q[(size_t)B_ * H_ * T_ * D_];          // [b][h][t][d]
__device__ float  g_k[(size_t)B_ * H_ * T_ * D_];          // [b][h][t][d]
__device__ __half g_v[(size_t)B_ * H_ * D_ * T_];          // [b][h][d][t]  (TRANSPOSED, fp16)
__device__ float  g_s[(size_t)B_ * H_ * T_ * T_];          // [b][h][q][k]  scores fp32
__device__ __half g_p[(size_t)B_ * H_ * T_ * T_];          // [b][h][q][k]  probs fp16
__device__ float  g_o[(size_t)B_ * T_ * C_];               // [b][t][h*64+d]

__device__ __forceinline__ float tf32_rna(float x) {
    float y;
    asm("cvt.rna.tf32.f32 %0, %1;" : "=f"(y) : "f"(x));
    return y;
}
__device__ __forceinline__ uint32_t smem_u32(const void* p) {
    uint32_t a;
    asm("{ .reg .u64 t; cvta.to.shared.u64 t, %1; cvt.u32.u64 %0, t; }" : "=r"(a) : "l"(p));
    return a;
}

// m16n8k8 tf32 mma (baseline PTX, maps to HMMA on sm_103)
#define MMA_TF32(c, a, b)                                                        \
    asm volatile("mma.sync.aligned.m16n8k8.row.col.f32.tf32.tf32.f32 "           \
                 "{%0,%1,%2,%3}, {%4,%5,%6,%7}, {%8,%9}, {%0,%1,%2,%3};"         \
                 : "+f"((c)[0]), "+f"((c)[1]), "+f"((c)[2]), "+f"((c)[3])        \
                 : "r"((a)[0]), "r"((a)[1]), "r"((a)[2]), "r"((a)[3]),           \
                   "r"((b)[0]), "r"((b)[1]))

// m16n8k16 fp16 mma, fp32 accumulate (baseline PTX, sm_70+)
#define MMA_F16(c, a, b)                                                         \
    asm volatile("mma.sync.aligned.m16n8k16.row.col.f32.f16.f16.f32 "            \
                 "{%0,%1,%2,%3}, {%4,%5,%6,%7}, {%8,%9}, {%0,%1,%2,%3};"         \
                 : "+f"((c)[0]), "+f"((c)[1]), "+f"((c)[2]), "+f"((c)[3])        \
                 : "r"((a)[0]), "r"((a)[1]), "r"((a)[2]), "r"((a)[3]),           \
                   "r"((b)[0]), "r"((b)[1]))

// ldmatrix (baseline PTX, sm_75+)
#define LDSM_X4(r, a)                                                            \
    asm volatile("ldmatrix.sync.aligned.m8n8.x4.shared.b16 {%0,%1,%2,%3}, [%4];" \
                 : "=r"((r)[0]), "=r"((r)[1]), "=r"((r)[2]), "=r"((r)[3])        \
                 : "r"(a))
#define LDSM_X2(r, a)                                                            \
    asm volatile("ldmatrix.sync.aligned.m8n8.x2.shared.b16 {%0,%1}, [%2];"       \
                 : "=r"((r)[0]), "=r"((r)[1])                                    \
                 : "r"(a))

// ============================================================================
// tf32 tensor-core GEMM (R12-proven):  C[m,n] = sum_k A[m,k] * B[n,k]  (NT)
// CTA: 128 x BN x 32, 256 thr (8 warps). ldmatrix fragment loads.
// SPLIT: 2-term tf32 split (hi*hi + hi*lo + lo*hi) -> fp32-class accuracy.
// MODE 0: QK proj -> out[((b*H+h)*T+t)*64+d]
// MODE 4: V proj  -> outH[((b*H+h)*64+d)*T+t]  (transposed, fp16)
// MODE 1: S       -> out[z*T*T + m*T + n] * 8
// MODE 3: O proj  -> out[m*C+n] + bias[n]
// ============================================================================
template <int MODE, bool SPLIT, int BN>
__global__ __launch_bounds__(256, 2) void mma_gemm(
    const float* __restrict__ A, const float* __restrict__ Bm,
    float* __restrict__ Cout, const float* __restrict__ bias,
    __half* __restrict__ CoutH,
    int K, int lda, int ldb, long long sA, long long sB)
{
    constexpr int BM = 128, BKP = 36;
    constexpr int GM = (BN == 128) ? 2 : 4;
    constexpr int WM = (BN == 128) ? 4 : 2;
    constexpr int WN = 4;
    constexpr int NA4 = 4;
    constexpr int NB4 = BN / 32;
    constexpr int ASZ = BM * BKP;
    constexpr int BSZ = BN * BKP;

    extern __shared__ float sm[];
    float* Ah = sm;
    float* Al = Ah + (SPLIT ? ASZ : 0);
    float* Bh = Ah + (SPLIT ? 2 : 1) * ASZ;
    float* Bl = Bh + (SPLIT ? BSZ : 0);

    const int tid = threadIdx.x;
    const int w   = tid >> 5;
    const int lane = tid & 31;
    const int gid = lane >> 2;
    const int tig = lane & 3;
    const int wm = w % GM;
    const int wn = w / GM;
    const int warp_m0 = wm * WM * 16;
    const int warp_n0 = wn * WN * 8;

    const int z = blockIdx.z;
    const float* Ab = A + (long long)z * sA;
    const float* Bb = Bm + (long long)z * sB;
    const int m0 = blockIdx.y * BM;
    const int n0 = blockIdx.x * BN;

    const int ar = tid >> 3;
    const int ac = (tid & 7) * 4;

    const int a_row = warp_m0 + (lane & 7) + ((lane >> 3) & 1) * 8;
    const int a_col = (lane >> 4) * 4;
    const uint32_t sAh = smem_u32(Ah) + (uint32_t)((a_row * BKP + a_col) * 4);
    const uint32_t sAl = sAh + (SPLIT ? ASZ * 4 : 0);
    const int b_lane = lane & 15;
    const int b_row = warp_n0 + (b_lane & 7);
    const int b_col = ((b_lane >> 3) & 1) * 4;
    const uint32_t sBh = smem_u32(Bh) + (uint32_t)((b_row * BKP + b_col) * 4);
    const uint32_t sBl = sBh + (SPLIT ? BSZ * 4 : 0);

    float acc[WM][WN][4];
#pragma unroll
    for (int i = 0; i < WM; i++)
#pragma unroll
        for (int j = 0; j < WN; j++)
#pragma unroll
            for (int t = 0; t < 4; t++) acc[i][j][t] = 0.0f;

    float4 pa[NA4], pb[NB4];
    auto loadA = [&](int k0) {
#pragma unroll
        for (int i = 0; i < NA4; i++)
            pa[i] = *(const float4*)(Ab + (long long)(m0 + ar + i * 32) * lda + k0 + ac);
    };
    auto loadB = [&](int k0) {
#pragma unroll
        for (int i = 0; i < NB4; i++)
            pb[i] = *(const float4*)(Bb + (long long)(n0 + ar + i * 32) * ldb + k0 + ac);
    };
    auto stage = [&]() {
#pragma unroll
        for (int i = 0; i < NA4; i++) {
            const int r = ar + i * 32;
            float4 h4, l4;
            h4.x = tf32_rna(pa[i].x); h4.y = tf32_rna(pa[i].y);
            h4.z = tf32_rna(pa[i].z); h4.w = tf32_rna(pa[i].w);
            *(float4*)&Ah[r * BKP + ac] = h4;
            if (SPLIT) {
                l4.x = tf32_rna(pa[i].x - h4.x); l4.y = tf32_rna(pa[i].y - h4.y);
                l4.z = tf32_rna(pa[i].z - h4.z); l4.w = tf32_rna(pa[i].w - h4.w);
                *(float4*)&Al[r * BKP + ac] = l4;
            }
        }
#pragma unroll
        for (int i = 0; i < NB4; i++) {
            const int r = ar + i * 32;
            float4 h4, l4;
            h4.x = tf32_rna(pb[i].x); h4.y = tf32_rna(pb[i].y);
            h4.z = tf32_rna(pb[i].z); h4.w = tf32_rna(pb[i].w);
            *(float4*)&Bh[r * BKP + ac] = h4;
            if (SPLIT) {
                l4.x = tf32_rna(pb[i].x - h4.x); l4.y = tf32_rna(pb[i].y - h4.y);
                l4.z = tf32_rna(pb[i].z - h4.z); l4.w = tf32_rna(pb[i].w - h4.w);
                *(float4*)&Bl[r * BKP + ac] = l4;
            }
        }
    };

    const int NC = K / 32;
    loadA(0); loadB(0);
    for (int c = 0; c < NC; c++) {
        __syncthreads();
        stage();
        __syncthreads();
        if (c + 1 < NC) { loadA((c + 1) * 32); loadB((c + 1) * 32); }

#pragma unroll
        for (int ks = 0; ks < 4; ks++) {
            uint32_t bh[WN][2], bl[WN][2];
#pragma unroll
            for (int nt = 0; nt < WN; nt++) {
                const uint32_t off = (uint32_t)((nt * 8 * BKP + ks * 8) * 4);
                LDSM_X2(bh[nt], sBh + off);
                if (SPLIT) LDSM_X2(bl[nt], sBl + off);
            }
#pragma unroll
            for (int mt = 0; mt < WM; mt++) {
                const uint32_t off = (uint32_t)((mt * 16 * BKP + ks * 8) * 4);
                uint32_t ah[4], al[4];
                LDSM_X4(ah, sAh + off);
                if (SPLIT) LDSM_X4(al, sAl + off);
#pragma unroll
                for (int nt = 0; nt < WN; nt++) {
                    MMA_TF32(acc[mt][nt], ah, bh[nt]);
                    if (SPLIT) {
                        MMA_TF32(acc[mt][nt], ah, bl[nt]);
                        MMA_TF32(acc[mt][nt], al, bh[nt]);
                    }
                }
            }
        }
    }

    // ---------------- epilogue ----------------
#pragma unroll
    for (int mt = 0; mt < WM; mt++) {
#pragma unroll
        for (int nt = 0; nt < WN; nt++) {
            const int m = m0 + warp_m0 + mt * 16 + gid;
            const int n = n0 + warp_n0 + nt * 8 + tig * 2;
            const float* cc = acc[mt][nt];
            if (MODE == 0) {
#pragma unroll
                for (int r = 0; r < 2; r++) {
                    const int mm = m + r * 8;
                    const int bb = mm >> 11, t = mm & (T_ - 1);
                    const int h = n >> 6, d0 = n & 63;
                    float2 f; f.x = cc[r * 2]; f.y = cc[r * 2 + 1];
                    *(float2*)&Cout[(((long long)(bb * H_ + h) * T_ + t) * D_) + d0] = f;
                }
            } else if (MODE == 4) {
                // V transposed, fp16: outH[((b*H+h)*64+d)*T + t]
#pragma unroll
                for (int r = 0; r < 2; r++) {
                    const int mm = m + r * 8;
                    const int bb = mm >> 11, t = mm & (T_ - 1);
#pragma unroll
                    for (int jj = 0; jj < 2; jj++) {
                        const int nn = n + jj;
                        const int h = nn >> 6, d0 = nn & 63;
                        CoutH[(((long long)(bb * H_ + h) * D_ + d0) * T_) + t] =
                            __float2half(cc[r * 2 + jj]);
                    }
                }
            } else if (MODE == 1) {
#pragma unroll
                for (int r = 0; r < 2; r++) {
                    float2 f; f.x = cc[r * 2] * 8.0f; f.y = cc[r * 2 + 1] * 8.0f;
                    *(float2*)&Cout[(long long)z * T_ * T_ + (long long)(m + r * 8) * T_ + n] = f;
                }
            } else {
#pragma unroll
                for (int r = 0; r < 2; r++) {
                    float2 f;
                    f.x = cc[r * 2]     + bias[n];
                    f.y = cc[r * 2 + 1] + bias[n + 1];
                    *(float2*)&Cout[(long long)(m + r * 8) * C_ + n] = f;
                }
            }
        }
    }
}

// ============================================================================
// PV fp16 GEMM: O[z, m, n] = sum_k P[z][m][k] * V[z][n][k]  (NT, fp16 in, fp32 out)
// CTA 128 x 64 x 32, 256 thr, warps 4m x 2n (warp 32x32), m16n8k16.
// Writes out[(b*T+m)*C + h*64 + n].
// ============================================================================
__global__ __launch_bounds__(256, 2) void pv_fp16(
    const __half* __restrict__ P, const __half* __restrict__ V,
    float* __restrict__ Cout)
{
    constexpr int PKP = 40;   // halves per smem row (32 + 8 pad)
    __shared__ __half Pt[128 * PKP];
    __shared__ __half Vt[64 * PKP];

    const int tid = threadIdx.x;
    const int w = tid >> 5, lane = tid & 31;
    const int gid = lane >> 2, tig = lane & 3;
    const int wm = w & 3, wn = w >> 2;
    const int warp_m0 = wm * 32, warp_n0 = wn * 32;
    const int z = blockIdx.z;
    const int m0 = blockIdx.y * 128;
    const __half* Pb = P + (long long)z * T_ * T_ + (long long)m0 * T_;
    const __half* Vb = V + (long long)z * D_ * T_;

    const int lr = tid >> 2;            // 0..63
    const int lc = (tid & 3) * 8;       // half offset, 16B granularity

    const uint32_t aBase = smem_u32(Pt) +
        (uint32_t)((warp_m0 + (lane & 15)) * PKP * 2 + (lane >> 4) * 16);
    const uint32_t bBase = smem_u32(Vt) +
        (uint32_t)((warp_n0 + (lane & 7)) * PKP * 2 + ((lane >> 3) & 1) * 16);

    float acc[2][4][4];
#pragma unroll
    for (int i = 0; i < 2; i++)
#pragma unroll
        for (int j = 0; j < 4; j++)
#pragma unroll
            for (int t = 0; t < 4; t++) acc[i][j][t] = 0.0f;

    uint4 pp0, pp1, pv;
    auto loadG = [&](int k0) {
        pp0 = *(const uint4*)(Pb + (long long)lr * T_ + k0 + lc);
        pp1 = *(const uint4*)(Pb + (long long)(lr + 64) * T_ + k0 + lc);
        pv  = *(const uint4*)(Vb + (long long)lr * T_ + k0 + lc);
    };
    auto stage = [&]() {
        *(uint4*)&Pt[lr * PKP + lc] = pp0;
        *(uint4*)&Pt[(lr + 64) * PKP + lc] = pp1;
        *(uint4*)&Vt[lr * PKP + lc] = pv;
    };

    loadG(0);
    const int NC = T_ / 32;
    for (int c = 0; c < NC; c++) {
        __syncthreads();
        stage();
        __syncthreads();
        if (c + 1 < NC) loadG((c + 1) * 32);
#pragma unroll
        for (int ks = 0; ks < 2; ks++) {
            uint32_t bh[4][2];
#pragma unroll
            for (int nt = 0; nt < 4; nt++)
                LDSM_X2(bh[nt], bBase + (uint32_t)(nt * 8 * PKP * 2 + ks * 32));
#pragma unroll
            for (int mt = 0; mt < 2; mt++) {
                uint32_t ah[4];
                LDSM_X4(ah, aBase + (uint32_t)(mt * 16 * PKP * 2 + ks * 32));
#pragma unroll
                for (int nt = 0; nt < 4; nt++)
                    MMA_F16(acc[mt][nt], ah, bh[nt]);
            }
        }
    }

    const int bb = z >> 4, h = z & 15;
#pragma unroll
    for (int mt = 0; mt < 2; mt++)
#pragma unroll
        for (int nt = 0; nt < 4; nt++) {
            const int m = m0 + warp_m0 + mt * 16 + gid;
            const int n = warp_n0 + nt * 8 + tig * 2;
            const float* cc = acc[mt][nt];
#pragma unroll
            for (int r = 0; r < 2; r++) {
                float2 f; f.x = cc[r * 2]; f.y = cc[r * 2 + 1];
                *(float2*)&Cout[((long long)(bb * T_ + m + r * 8)) * C_ + h * D_ + n] = f;
            }
        }
}

// ---------------------------------------------------------------------------
// Head-axis softmax (quirk: softmax over dim=1 == H). Reads fp32 S, writes fp16 P.
// ---------------------------------------------------------------------------
__global__ __launch_bounds__(256) void softmax_head_kernel(const float* __restrict__ s,
                                                           __half* __restrict__ p)
{
    const long long idx = (long long)blockIdx.x * blockDim.x + threadIdx.x; // B*T*(T/4)
    const long long hs = (long long)T_ * T_;
    const int k4 = (int)(idx & (T_ / 4 - 1)) * 4;
    const long long bq = idx >> 9;
    const int b = (int)(bq >> 11);
    const int q = (int)(bq & (T_ - 1));
    const long long base = (((long long)b * H_) * T_ + q) * T_ + k4;

    float4 v[H_];
    float4 mx = make_float4(-1e30f, -1e30f, -1e30f, -1e30f);
#pragma unroll
    for (int h = 0; h < H_; h++) {
        v[h] = *(const float4*)&s[base + (long long)h * hs];
        mx.x = fmaxf(mx.x, v[h].x); mx.y = fmaxf(mx.y, v[h].y);
        mx.z = fmaxf(mx.z, v[h].z); mx.w = fmaxf(mx.w, v[h].w);
    }
    float4 sum = make_float4(0.f, 0.f, 0.f, 0.f);
#pragma unroll
    for (int h = 0; h < H_; h++) {
        v[h].x = __expf(v[h].x - mx.x); v[h].y = __expf(v[h].y - mx.y);
        v[h].z = __expf(v[h].z - mx.z); v[h].w = __expf(v[h].w - mx.w);
        sum.x += v[h].x; sum.y += v[h].y; sum.z += v[h].z; sum.w += v[h].w;
    }
    const float ix = 1.0f / sum.x, iy = 1.0f / sum.y;
    const float iz = 1.0f / sum.z, iw = 1.0f / sum.w;
#pragma unroll
    for (int h = 0; h < H_; h++) {
        __half2 h01 = __floats2half2_rn(v[h].x * ix, v[h].y * iy);
        __half2 h23 = __floats2half2_rn(v[h].z * iz, v[h].w * iw);
        uint2 pk;
        pk.x = *(uint32_t*)&h01;
        pk.y = *(uint32_t*)&h23;
        *(uint2*)&p[base + (long long)h * hs] = pk;
    }
}

// ---------------------------------------------------------------------------
extern "C" void kernel_launch(void* const* d_in, const int* in_sizes, int n_in,
                              void* d_out, int out_size)
{
    const float* query_src = (const float*)d_in[0];
    const float* key_src   = (const float*)d_in[1];
    const float* value_src = (const float*)d_in[2];
    const float* Wq        = (const float*)d_in[3];
    const float* Wk        = (const float*)d_in[4];
    const float* Wv        = (const float*)d_in[5];
    const float* Wo        = (const float*)d_in[6];
    const float* bo        = (const float*)d_in[7];
    float* out = (float*)d_out;

    float *q, *k, *s, *o;
    __half *v, *p;
    cudaGetSymbolAddress((void**)&q, g_q);
    cudaGetSymbolAddress((void**)&k, g_k);
    cudaGetSymbolAddress((void**)&v, g_v);
    cudaGetSymbolAddress((void**)&s, g_s);
    cudaGetSymbolAddress((void**)&p, g_p);
    cudaGetSymbolAddress((void**)&o, g_o);

    const int SM_SPLIT128  = (2 * 128 + 2 * 128) * 36 * 4;  // 73728
    const int SM_SINGLE128 = (128 + 128) * 36 * 4;          // 36864
    cudaFuncSetAttribute(mma_gemm<0, true, 128>, cudaFuncAttributeMaxDynamicSharedMemorySize, SM_SPLIT128);
    cudaFuncSetAttribute(mma_gemm<4, false, 128>, cudaFuncAttributeMaxDynamicSharedMemorySize, SM_SINGLE128);
    cudaFuncSetAttribute(mma_gemm<1, true, 128>, cudaFuncAttributeMaxDynamicSharedMemorySize, SM_SPLIT128);
    cudaFuncSetAttribute(mma_gemm<3, false, 128>, cudaFuncAttributeMaxDynamicSharedMemorySize, SM_SINGLE128);

    const dim3 blk(256);

    // Pass 1: projections.  Q,K split tf32 -> [b,h,t,d]; V single tf32 -> fp16 [b,h,d,t]
    {
        dim3 grid(C_ / 128, (B_ * T_) / 128, 1);
        mma_gemm<0, true, 128><<<grid, blk, SM_SPLIT128>>>(query_src, Wq, q, nullptr, nullptr, C_, C_, C_, 0, 0);
        mma_gemm<0, true, 128><<<grid, blk, SM_SPLIT128>>>(key_src,   Wk, k, nullptr, nullptr, C_, C_, C_, 0, 0);
        mma_gemm<4, false, 128><<<grid, blk, SM_SINGLE128>>>(value_src, Wv, nullptr, nullptr, v, C_, C_, C_, 0, 0);
    }
    // Pass 2: S[b,h,q,k] = 8 * q.k   (split tf32)
    {
        dim3 grid(T_ / 128, T_ / 128, B_ * H_);
        mma_gemm<1, true, 128><<<grid, blk, SM_SPLIT128>>>(q, k, s, nullptr, nullptr, D_, D_, D_,
                                                           (long long)T_ * D_, (long long)T_ * D_);
    }
    // Pass 3: softmax over HEAD axis: fp32 S -> fp16 P
    {
        const long long total = (long long)B_ * T_ * (T_ / 4);
        softmax_head_kernel<<<(unsigned)(total / 256), 256>>>(s, p);
    }
    // Pass 4: O = P @ V^T_stored (fp16 mma) -> [b][q][h*64+d] fp32
    {
        dim3 grid(1, T_ / 128, B_ * H_);
        pv_fp16<<<grid, blk>>>(p, v, o);
    }
    // Pass 5: out = O @ Wo^T + bo   (single tf32)
    {
        dim3 grid(C_ / 128, (B_ * T_) / 128, 1);
        mma_gemm<3, false, 128><<<grid, blk, SM_SINGLE128>>>(o, Wo, out, bo, nullptr, C_, C_, C_, 0, 0);
    }
}

// round 15
// speedup vs baseline: 2.0558x; 1.2319x over previous
#include <cuda_runtime.h>
#include <cuda_fp16.h>
#include <cstdint>

#define B_ 2
#define T_ 2048
#define C_ 1024
#define H_ 16
#define D_ 64

// ---- scratch (no cudaMalloc allowed) ----
__device__ __half g_q[(size_t)B_ * H_ * T_ * 2 * D_];      // [z][t][hi(64)|lo(64)] fp16
__device__ __half g_k[(size_t)B_ * H_ * T_ * 2 * D_];
__device__ __half g_v[(size_t)B_ * H_ * D_ * T_];          // [b][h][d][t] fp16 (transposed)
__device__ float  g_s[(size_t)B_ * H_ * T_ * T_];          // scores fp32
__device__ __half g_p[(size_t)B_ * H_ * T_ * T_];          // probs fp16
__device__ float  g_o[(size_t)B_ * T_ * C_];               // [b][t][h*64+d]

__device__ __forceinline__ uint32_t smem_u32(const void* p) {
    uint32_t a;
    asm("{ .reg .u64 t; cvta.to.shared.u64 t, %1; cvt.u32.u64 %0, t; }" : "=r"(a) : "l"(p));
    return a;
}

// m16n8k16 fp16 mma, fp32 accumulate (baseline PTX, sm_70+)
#define MMA_F16(c, a, b)                                                         \
    asm volatile("mma.sync.aligned.m16n8k16.row.col.f32.f16.f16.f32 "            \
                 "{%0,%1,%2,%3}, {%4,%5,%6,%7}, {%8,%9}, {%0,%1,%2,%3};"         \
                 : "+f"((c)[0]), "+f"((c)[1]), "+f"((c)[2]), "+f"((c)[3])        \
                 : "r"((a)[0]), "r"((a)[1]), "r"((a)[2]), "r"((a)[3]),           \
                   "r"((b)[0]), "r"((b)[1]))

#define LDSM_X4(r, a)                                                            \
    asm volatile("ldmatrix.sync.aligned.m8n8.x4.shared.b16 {%0,%1,%2,%3}, [%4];" \
                 : "=r"((r)[0]), "=r"((r)[1]), "=r"((r)[2]), "=r"((r)[3])        \
                 : "r"(a))
#define LDSM_X2(r, a)                                                            \
    asm volatile("ldmatrix.sync.aligned.m8n8.x2.shared.b16 {%0,%1}, [%2];"       \
                 : "=r"((r)[0]), "=r"((r)[1])                                    \
                 : "r"(a))

// ============================================================================
// fp16 projection GEMM:  C[m,n] = sum_k A[m,k] * B[n,k]  (NT), fp32 inputs.
// CTA 128x128x32, 256 thr, warps 2m x 4n (warp 64x32), m16n8k16.
// SPLIT: 2-term fp16 split (hi*hi + hi*lo + lo*hi) -> fp32-class accuracy.
// MODE 0: Q/K proj -> CoutH[((b*16+h)*T+t)*128 + d] = hi, +64 = lo   (pre-split)
// MODE 4: V proj   -> CoutH[((b*16+h)*64+d)*T + t]                   (transposed)
// MODE 3: O proj   -> Cout[m*C+n] + bias[n]                          (fp32)
// ============================================================================
template <int MODE, bool SPLIT>
__global__ __launch_bounds__(256, 2) void proj_f16(
    const float* __restrict__ A, const float* __restrict__ Bm,
    float* __restrict__ Cout, const float* __restrict__ bias,
    __half* __restrict__ CoutH, int K, int lda, int ldb)
{
    constexpr int HKP = 40;                    // halves per smem row (32 + 8 pad)
    constexpr int ROWB = HKP * 2;              // 80 bytes
    constexpr int TSZ = 128 * HKP;             // halves per tile
    __shared__ __half smh[(SPLIT ? 4 : 2) * TSZ];
    __half* Ah = smh;
    __half* Al = Ah + (SPLIT ? TSZ : 0);
    __half* Bh = Ah + (SPLIT ? 2 : 1) * TSZ;
    __half* Bl = Bh + (SPLIT ? TSZ : 0);

    const int tid = threadIdx.x;
    const int w = tid >> 5, lane = tid & 31;
    const int gid = lane >> 2, tig = lane & 3;
    const int wm = w & 1, wn = w >> 1;
    const int warp_m0 = wm * 64;               // 4 m16 tiles
    const int warp_n0 = wn * 32;               // 4 n8 tiles

    const int m0 = blockIdx.y * 128;
    const int n0 = blockIdx.x * 128;

    // staging: thread -> row sr (0..127), float cols sc..sc+15
    const int sr = tid >> 1;
    const int sc = (tid & 1) * 16;

    // fragment base addresses (proven mapping from pv_fp16)
    const uint32_t aB = smem_u32(Ah) + (uint32_t)((warp_m0 + (lane & 15)) * ROWB + (lane >> 4) * 16);
    const uint32_t bB = smem_u32(Bh) + (uint32_t)((warp_n0 + (lane & 7)) * ROWB + ((lane >> 3) & 1) * 16);
    constexpr uint32_t LOFF = (uint32_t)TSZ * 2;   // hi->lo byte offset

    float acc[4][4][4];
#pragma unroll
    for (int i = 0; i < 4; i++)
#pragma unroll
        for (int j = 0; j < 4; j++)
#pragma unroll
            for (int t = 0; t < 4; t++) acc[i][j][t] = 0.0f;

    float4 pa[4], pb[4];
    auto loadA = [&](int k0) {
#pragma unroll
        for (int i = 0; i < 4; i++)
            pa[i] = *(const float4*)(A + (long long)(m0 + sr) * lda + k0 + sc + i * 4);
    };
    auto loadB = [&](int k0) {
#pragma unroll
        for (int i = 0; i < 4; i++)
            pb[i] = *(const float4*)(Bm + (long long)(n0 + sr) * ldb + k0 + sc + i * 4);
    };
    auto stageMat = [&](const float4* p, __half* Mh, __half* Ml) {
        uint32_t hu[8], lu[8];
#pragma unroll
        for (int i = 0; i < 4; i++) {
            __half2 h0 = __floats2half2_rn(p[i].x, p[i].y);
            __half2 h1 = __floats2half2_rn(p[i].z, p[i].w);
            hu[i * 2]     = *(uint32_t*)&h0;
            hu[i * 2 + 1] = *(uint32_t*)&h1;
            if (SPLIT) {
                __half2 l0 = __floats2half2_rn(p[i].x - __low2float(h0), p[i].y - __high2float(h0));
                __half2 l1 = __floats2half2_rn(p[i].z - __low2float(h1), p[i].w - __high2float(h1));
                lu[i * 2]     = *(uint32_t*)&l0;
                lu[i * 2 + 1] = *(uint32_t*)&l1;
            }
        }
        uint4* d = (uint4*)&Mh[sr * HKP + sc];
        d[0] = make_uint4(hu[0], hu[1], hu[2], hu[3]);
        d[1] = make_uint4(hu[4], hu[5], hu[6], hu[7]);
        if (SPLIT) {
            uint4* dl = (uint4*)&Ml[sr * HKP + sc];
            dl[0] = make_uint4(lu[0], lu[1], lu[2], lu[3]);
            dl[1] = make_uint4(lu[4], lu[5], lu[6], lu[7]);
        }
    };

    const int NC = K / 32;
    loadA(0); loadB(0);
    for (int c = 0; c < NC; c++) {
        __syncthreads();
        stageMat(pa, Ah, Al);
        stageMat(pb, Bh, Bl);
        __syncthreads();
        if (c + 1 < NC) { loadA((c + 1) * 32); loadB((c + 1) * 32); }

#pragma unroll
        for (int ks = 0; ks < 2; ks++) {
            uint32_t bh[4][2], bl[4][2];
#pragma unroll
            for (int nt = 0; nt < 4; nt++) {
                const uint32_t off = (uint32_t)(nt * 8 * ROWB + ks * 32);
                LDSM_X2(bh[nt], bB + off);
                if (SPLIT) LDSM_X2(bl[nt], bB + LOFF + off);
            }
#pragma unroll
            for (int mt = 0; mt < 4; mt++) {
                const uint32_t off = (uint32_t)(mt * 16 * ROWB + ks * 32);
                uint32_t ah[4], al[4];
                LDSM_X4(ah, aB + off);
                if (SPLIT) LDSM_X4(al, aB + LOFF + off);
#pragma unroll
                for (int nt = 0; nt < 4; nt++) {
                    MMA_F16(acc[mt][nt], ah, bh[nt]);
                    if (SPLIT) {
                        MMA_F16(acc[mt][nt], ah, bl[nt]);
                        MMA_F16(acc[mt][nt], al, bh[nt]);
                    }
                }
            }
        }
    }

    // ---------------- epilogue ----------------
#pragma unroll
    for (int mt = 0; mt < 4; mt++) {
#pragma unroll
        for (int nt = 0; nt < 4; nt++) {
            const int m = m0 + warp_m0 + mt * 16 + gid;
            const int n = n0 + warp_n0 + nt * 8 + tig * 2;
            const float* cc = acc[mt][nt];
#pragma unroll
            for (int r = 0; r < 2; r++) {
                const int mm = m + r * 8;
                const float v0 = cc[r * 2], v1 = cc[r * 2 + 1];
                if (MODE == 0) {
                    const int bb = mm >> 11, t = mm & (T_ - 1);
                    const int h = n >> 6, d0 = n & 63;
                    const long long base =
                        ((long long)(bb * H_ + h) * T_ + t) * (2 * D_) + d0;
                    __half h0 = __float2half_rn(v0);
                    __half h1 = __float2half_rn(v1);
                    __half l0 = __float2half_rn(v0 - __half2float(h0));
                    __half l1 = __float2half_rn(v1 - __half2float(h1));
                    *(__half2*)&CoutH[base]      = __halves2half2(h0, h1);
                    *(__half2*)&CoutH[base + D_] = __halves2half2(l0, l1);
                } else if (MODE == 4) {
                    const int bb = mm >> 11, t = mm & (T_ - 1);
#pragma unroll
                    for (int jj = 0; jj < 2; jj++) {
                        const int nn = n + jj;
                        const int h = nn >> 6, d0 = nn & 63;
                        CoutH[(((long long)(bb * H_ + h) * D_ + d0) * T_) + t] =
                            __float2half(jj ? v1 : v0);
                    }
                } else {
                    float2 f;
                    f.x = v0 + bias[n];
                    f.y = v1 + bias[n + 1];
                    *(float2*)&Cout[(long long)mm * C_ + n] = f;
                }
            }
        }
    }
}

// ============================================================================
// S kernel: S[z,m,n] = 8 * sum_d q[z,m,:] . k[z,n,:]  via fp16 3-term split.
// q,k pre-split fp16 [z][t][hi(64)|lo(64)]. CTA 128x128, K=64, no chunk loop.
// ============================================================================
__global__ __launch_bounds__(256, 2) void s_f16(
    const __half* __restrict__ Q, const __half* __restrict__ Kx,
    float* __restrict__ S)
{
    constexpr int SKP = 136;                 // halves per smem row (128 + 8)
    constexpr int ROWB = SKP * 2;            // 272 bytes
    extern __shared__ __half sh[];
    __half* Aq = sh;
    __half* Bk = sh + 128 * SKP;

    const int tid = threadIdx.x;
    const int w = tid >> 5, lane = tid & 31;
    const int gid = lane >> 2, tig = lane & 3;
    const int wm = w & 1, wn = w >> 1;
    const int warp_m0 = wm * 64;
    const int warp_n0 = wn * 32;

    const int z = blockIdx.z;
    const int m0 = blockIdx.y * 128;
    const int n0 = blockIdx.x * 128;
    const __half* Qb = Q + (long long)z * T_ * (2 * D_) + (long long)m0 * (2 * D_);
    const __half* Kb = Kx + (long long)z * T_ * (2 * D_) + (long long)n0 * (2 * D_);

    // staging: 2 threads per row, 128 bytes each (one-time)
    const int sr = tid >> 1;
    const int ss = (tid & 1) * 64;           // half offset
    {
        const uint4* qa = (const uint4*)(Qb + (long long)sr * (2 * D_) + ss);
        uint4* da = (uint4*)&Aq[sr * SKP + ss];
#pragma unroll
        for (int i = 0; i < 8; i++) da[i] = qa[i];
        const uint4* kb = (const uint4*)(Kb + (long long)sr * (2 * D_) + ss);
        uint4* db = (uint4*)&Bk[sr * SKP + ss];
#pragma unroll
        for (int i = 0; i < 8; i++) db[i] = kb[i];
    }
    __syncthreads();

    const uint32_t aB = smem_u32(Aq) + (uint32_t)((warp_m0 + (lane & 15)) * ROWB + (lane >> 4) * 16);
    const uint32_t bB = smem_u32(Bk) + (uint32_t)((warp_n0 + (lane & 7)) * ROWB + ((lane >> 3) & 1) * 16);
    constexpr uint32_t LOFF = 128;           // hi->lo byte offset within a row

    float acc[4][4][4];
#pragma unroll
    for (int i = 0; i < 4; i++)
#pragma unroll
        for (int j = 0; j < 4; j++)
#pragma unroll
            for (int t = 0; t < 4; t++) acc[i][j][t] = 0.0f;

#pragma unroll
    for (int ks = 0; ks < 4; ks++) {
        uint32_t bh[4][2], bl[4][2];
#pragma unroll
        for (int nt = 0; nt < 4; nt++) {
            const uint32_t off = (uint32_t)(nt * 8 * ROWB + ks * 32);
            LDSM_X2(bh[nt], bB + off);
            LDSM_X2(bl[nt], bB + LOFF + off);
        }
#pragma unroll
        for (int mt = 0; mt < 4; mt++) {
            const uint32_t off = (uint32_t)(mt * 16 * ROWB + ks * 32);
            uint32_t ah[4], al[4];
            LDSM_X4(ah, aB + off);
            LDSM_X4(al, aB + LOFF + off);
#pragma unroll
            for (int nt = 0; nt < 4; nt++) {
                MMA_F16(acc[mt][nt], ah, bh[nt]);
                MMA_F16(acc[mt][nt], ah, bl[nt]);
                MMA_F16(acc[mt][nt], al, bh[nt]);
            }
        }
    }

#pragma unroll
    for (int mt = 0; mt < 4; mt++)
#pragma unroll
        for (int nt = 0; nt < 4; nt++) {
            const int m = m0 + warp_m0 + mt * 16 + gid;
            const int n = n0 + warp_n0 + nt * 8 + tig * 2;
            const float* cc = acc[mt][nt];
#pragma unroll
            for (int r = 0; r < 2; r++) {
                float2 f; f.x = cc[r * 2] * 8.0f; f.y = cc[r * 2 + 1] * 8.0f;
                *(float2*)&S[(long long)z * T_ * T_ + (long long)(m + r * 8) * T_ + n] = f;
            }
        }
}

// ============================================================================
// PV fp16 GEMM (R14-proven): O = P @ V^T_stored, fp16 in, fp32 out.
// ============================================================================
__global__ __launch_bounds__(256, 2) void pv_fp16(
    const __half* __restrict__ P, const __half* __restrict__ V,
    float* __restrict__ Cout)
{
    constexpr int PKP = 40;
    __shared__ __half Pt[128 * PKP];
    __shared__ __half Vt[64 * PKP];

    const int tid = threadIdx.x;
    const int w = tid >> 5, lane = tid & 31;
    const int gid = lane >> 2, tig = lane & 3;
    const int wm = w & 3, wn = w >> 2;
    const int warp_m0 = wm * 32, warp_n0 = wn * 32;
    const int z = blockIdx.z;
    const int m0 = blockIdx.y * 128;
    const __half* Pb = P + (long long)z * T_ * T_ + (long long)m0 * T_;
    const __half* Vb = V + (long long)z * D_ * T_;

    const int lr = tid >> 2;
    const int lc = (tid & 3) * 8;

    const uint32_t aBase = smem_u32(Pt) +
        (uint32_t)((warp_m0 + (lane & 15)) * PKP * 2 + (lane >> 4) * 16);
    const uint32_t bBase = smem_u32(Vt) +
        (uint32_t)((warp_n0 + (lane & 7)) * PKP * 2 + ((lane >> 3) & 1) * 16);

    float acc[2][4][4];
#pragma unroll
    for (int i = 0; i < 2; i++)
#pragma unroll
        for (int j = 0; j < 4; j++)
#pragma unroll
            for (int t = 0; t < 4; t++) acc[i][j][t] = 0.0f;

    uint4 pp0, pp1, pv;
    auto loadG = [&](int k0) {
        pp0 = *(const uint4*)(Pb + (long long)lr * T_ + k0 + lc);
        pp1 = *(const uint4*)(Pb + (long long)(lr + 64) * T_ + k0 + lc);
        pv  = *(const uint4*)(Vb + (long long)lr * T_ + k0 + lc);
    };
    auto stage = [&]() {
        *(uint4*)&Pt[lr * PKP + lc] = pp0;
        *(uint4*)&Pt[(lr + 64) * PKP + lc] = pp1;
        *(uint4*)&Vt[lr * PKP + lc] = pv;
    };

    loadG(0);
    const int NC = T_ / 32;
    for (int c = 0; c < NC; c++) {
        __syncthreads();
        stage();
        __syncthreads();
        if (c + 1 < NC) loadG((c + 1) * 32);
#pragma unroll
        for (int ks = 0; ks < 2; ks++) {
            uint32_t bh[4][2];
#pragma unroll
            for (int nt = 0; nt < 4; nt++)
                LDSM_X2(bh[nt], bBase + (uint32_t)(nt * 8 * PKP * 2 + ks * 32));
#pragma unroll
            for (int mt = 0; mt < 2; mt++) {
                uint32_t ah[4];
                LDSM_X4(ah, aBase + (uint32_t)(mt * 16 * PKP * 2 + ks * 32));
#pragma unroll
                for (int nt = 0; nt < 4; nt++)
                    MMA_F16(acc[mt][nt], ah, bh[nt]);
            }
        }
    }

    const int bb = z >> 4, h = z & 15;
#pragma unroll
    for (int mt = 0; mt < 2; mt++)
#pragma unroll
        for (int nt = 0; nt < 4; nt++) {
            const int m = m0 + warp_m0 + mt * 16 + gid;
            const int n = warp_n0 + nt * 8 + tig * 2;
            const float* cc = acc[mt][nt];
#pragma unroll
            for (int r = 0; r < 2; r++) {
                float2 f; f.x = cc[r * 2]; f.y = cc[r * 2 + 1];
                *(float2*)&Cout[((long long)(bb * T_ + m + r * 8)) * C_ + h * D_ + n] = f;
            }
        }
}

// ---------------------------------------------------------------------------
// Head-axis softmax (quirk: softmax over dim=1 == H). fp32 S -> fp16 P.
// ---------------------------------------------------------------------------
__global__ __launch_bounds__(256) void softmax_head_kernel(const float* __restrict__ s,
                                                           __half* __restrict__ p)
{
    const long long idx = (long long)blockIdx.x * blockDim.x + threadIdx.x;
    const long long hs = (long long)T_ * T_;
    const int k4 = (int)(idx & (T_ / 4 - 1)) * 4;
    const long long bq = idx >> 9;
    const int b = (int)(bq >> 11);
    const int q = (int)(bq & (T_ - 1));
    const long long base = (((long long)b * H_) * T_ + q) * T_ + k4;

    float4 v[H_];
    float4 mx = make_float4(-1e30f, -1e30f, -1e30f, -1e30f);
#pragma unroll
    for (int h = 0; h < H_; h++) {
        v[h] = *(const float4*)&s[base + (long long)h * hs];
        mx.x = fmaxf(mx.x, v[h].x); mx.y = fmaxf(mx.y, v[h].y);
        mx.z = fmaxf(mx.z, v[h].z); mx.w = fmaxf(mx.w, v[h].w);
    }
    float4 sum = make_float4(0.f, 0.f, 0.f, 0.f);
#pragma unroll
    for (int h = 0; h < H_; h++) {
        v[h].x = __expf(v[h].x - mx.x); v[h].y = __expf(v[h].y - mx.y);
        v[h].z = __expf(v[h].z - mx.z); v[h].w = __expf(v[h].w - mx.w);
        sum.x += v[h].x; sum.y += v[h].y; sum.z += v[h].z; sum.w += v[h].w;
    }
    const float ix = 1.0f / sum.x, iy = 1.0f / sum.y;
    const float iz = 1.0f / sum.z, iw = 1.0f / sum.w;
#pragma unroll
    for (int h = 0; h < H_; h++) {
        __half2 h01 = __floats2half2_rn(v[h].x * ix, v[h].y * iy);
        __half2 h23 = __floats2half2_rn(v[h].z * iz, v[h].w * iw);
        uint2 pk;
        pk.x = *(uint32_t*)&h01;
        pk.y = *(uint32_t*)&h23;
        *(uint2*)&p[base + (long long)h * hs] = pk;
    }
}

// ---------------------------------------------------------------------------
extern "C" void kernel_launch(void* const* d_in, const int* in_sizes, int n_in,
                              void* d_out, int out_size)
{
    const float* query_src = (const float*)d_in[0];
    const float* key_src   = (const float*)d_in[1];
    const float* value_src = (const float*)d_in[2];
    const float* Wq        = (const float*)d_in[3];
    const float* Wk        = (const float*)d_in[4];
    const float* Wv        = (const float*)d_in[5];
    const float* Wo        = (const float*)d_in[6];
    const float* bo        = (const float*)d_in[7];
    float* out = (float*)d_out;

    __half *q, *k, *v, *p;
    float *s, *o;
    cudaGetSymbolAddress((void**)&q, g_q);
    cudaGetSymbolAddress((void**)&k, g_k);
    cudaGetSymbolAddress((void**)&v, g_v);
    cudaGetSymbolAddress((void**)&s, g_s);
    cudaGetSymbolAddress((void**)&p, g_p);
    cudaGetSymbolAddress((void**)&o, g_o);

    const int SM_S = 2 * 128 * 136 * 2;   // 69632 bytes dynamic for s_f16
    cudaFuncSetAttribute(s_f16, cudaFuncAttributeMaxDynamicSharedMemorySize, SM_S);

    const dim3 blk(256);

    // Pass 1: projections.
    //   Q,K: fp16 3-term split -> pre-split fp16 [z][t][hi|lo]
    //   V:   fp16 single -> transposed fp16 [b,h,d,t]
    {
        dim3 grid(C_ / 128, (B_ * T_) / 128, 1);
        proj_f16<0, true><<<grid, blk>>>(query_src, Wq, nullptr, nullptr, q, C_, C_, C_);
        proj_f16<0, true><<<grid, blk>>>(key_src,   Wk, nullptr, nullptr, k, C_, C_, C_);
        proj_f16<4, false><<<grid, blk>>>(value_src, Wv, nullptr, nullptr, v, C_, C_, C_);
    }
    // Pass 2: S = 8 * q.k (fp16 3-term split, K=64)
    {
        dim3 grid(T_ / 128, T_ / 128, B_ * H_);
        s_f16<<<grid, blk, SM_S>>>(q, k, s);
    }
    // Pass 3: softmax over HEAD axis: fp32 S -> fp16 P
    {
        const long long total = (long long)B_ * T_ * (T_ / 4);
        softmax_head_kernel<<<(unsigned)(total / 256), 256>>>(s, p);
    }
    // Pass 4: O = P @ V (fp16 mma) -> fp32 [b][q][h*64+d]
    {
        dim3 grid(1, T_ / 128, B_ * H_);
        pv_fp16<<<grid, blk>>>(p, v, o);
    }
    // Pass 5: out = O @ Wo^T + bo (fp16 single)
    {
        dim3 grid(C_ / 128, (B_ * T_) / 128, 1);
        proj_f16<3, false><<<grid, blk>>>(o, Wo, out, bo, nullptr, C_, C_, C_);
    }
}